// round 17
// baseline (speedup 1.0000x reference)
#include <cuda_runtime.h>

// Grouped 3-tap width conv with cyclic rolls, fp32.
// Grid = 16 k-tiles x 8 i-splits = 128 blocks, 448 threads (14 warps).
// Warp = (height n, i-half): same mainloop as before, but a block's distinct
// weight footprint is 24 KB (not 196 KB) and 7 warps share it -> L1-resident.
// Cross-block i-split merged via atomicAdd into memset-zeroed out.
//
// y[o,k,n,m] = sum_{i,j} f[o,i,m+j] * w[i,k,j],  f[1..7] = width-rolled x row,
// f[0]=f[8]=0 (taps dropped); height roll baked into the atomic store index.

#define THREADS  448

#define OFF_IN   0
#define SZ_IN    (448 * 64)            // 28672: rows [n*64 + ih*32 + il], 7 f2 slots
#define OFF_RED  SZ_IN                 // 12544: partials from ih=1 warps
#define SZ_RED   (7 * 32 * 7 * 8)
#define SMEM_TOT (OFF_RED + SZ_RED)    // 41216 (< 48KB, no attribute needed)

typedef unsigned long long ull;

__device__ __forceinline__ ull ffma2(ull a, ull b, ull c)
{
    ull d;
    asm("fma.rn.f32x2 %0, %1, %2, %3;" : "=l"(d) : "l"(a), "l"(b), "l"(c));
    return d;
}
__device__ __forceinline__ ull dup2(float v)
{
    ull d;
    asm("mov.b64 %0, {%1, %1};" : "=l"(d) : "f"(v));
    return d;
}

__global__ __launch_bounds__(THREADS, 1) void conv_l1w(const float* __restrict__ x,
                                                       const float* __restrict__ w,
                                                       float* __restrict__ out)
{
    extern __shared__ char sm[];
    const int tid = threadIdx.x, warp = tid >> 5, lane = tid & 31;
    const int kb  = blockIdx.x;          // 0..15
    const int isp = blockIdx.y;          // 0..7
    const int k0  = kb * 32;
    const int n   = warp / 2;            // 0..6
    const int ih  = warp & 1;            // i-half
    const int iG  = isp * 64 + ih * 32;  // global i base for this warp
    const int rowB = n * 64 + ih * 32;   // smem row base

    // ---- weight register pipeline: 4 chunks of 8 i, 3 buffers ----
    const float* wl = w + (long)iG * 1536 + (k0 + lane) * 3;

    float a0[8], a1[8], a2[8];
    float b0[8], b1[8], b2[8];
    float c0[8], c1[8], c2[8];

#define LOADW(d0, d1, d2, c) do { \
        const float* p_ = wl + (c) * (8 * 1536); \
        _Pragma("unroll") \
        for (int t = 0; t < 8; t++) { \
            d0[t] = p_[t * 1536]; \
            d1[t] = p_[t * 1536 + 1]; \
            d2[t] = p_[t * 1536 + 2]; \
        } \
    } while (0)

    LOADW(a0, a1, a2, 0);                // ride the staging latency shadow
    LOADW(b0, b1, b2, 1);
    LOADW(c0, c1, c2, 2);

    // ---- warp-private input staging: 64 rows (32 i x 2 groups) at height n ----
    {
        int rl = lane / 7;               // local row 0..63 = o*32 + il
        int j  = lane - rl * 7;          // source width position
        const int nbase = n * 7;
#pragma unroll
        for (int q = 0; q < 14; q++) {
            int o  = rl >> 5, il = rl & 31;
            float v = x[(o * 512 + iG + il) * 49 + nbase + j];
            int u = (j == 6) ? 1 : (j + 2);            // width roll +1
            *reinterpret_cast<float*>(sm + OFF_IN + (rowB + il) * 64 + (u - 1) * 8 + o * 4) = v;
            j += 4;
            if (j >= 7) { j -= 7; rl += 5; } else rl += 4;
        }
    }
    __syncwarp();                        // own slice visible; no block barrier

    ull A[7];
#pragma unroll
    for (int m = 0; m < 7; m++) A[m] = 0ull;

#define COMPUTE(c, s0, s1, s2) do { \
        const char* ip_ = sm + OFF_IN + ((rowB + (c) * 8) << 6); \
        _Pragma("unroll") \
        for (int t = 0; t < 8; t++) { \
            const char* ib = ip_ + t * 64; \
            ulonglong2 L0 = *reinterpret_cast<const ulonglong2*>(ib);       /* f1,f2 */ \
            ulonglong2 L1 = *reinterpret_cast<const ulonglong2*>(ib + 16);  /* f3,f4 */ \
            ulonglong2 L2 = *reinterpret_cast<const ulonglong2*>(ib + 32);  /* f5,f6 */ \
            ull        p7 = *reinterpret_cast<const ull*>(ib + 48);         /* f7 */ \
            ull W0 = dup2(s0[t]), W1 = dup2(s1[t]), W2 = dup2(s2[t]); \
            ull p1 = L0.x, p2 = L0.y, p3 = L1.x, p4 = L1.y, p5 = L2.x, p6 = L2.y; \
            A[0] = ffma2(p1, W1, A[0]); A[0] = ffma2(p2, W2, A[0]); \
            A[1] = ffma2(p1, W0, A[1]); A[1] = ffma2(p2, W1, A[1]); A[1] = ffma2(p3, W2, A[1]); \
            A[2] = ffma2(p2, W0, A[2]); A[2] = ffma2(p3, W1, A[2]); A[2] = ffma2(p4, W2, A[2]); \
            A[3] = ffma2(p3, W0, A[3]); A[3] = ffma2(p4, W1, A[3]); A[3] = ffma2(p5, W2, A[3]); \
            A[4] = ffma2(p4, W0, A[4]); A[4] = ffma2(p5, W1, A[4]); A[4] = ffma2(p6, W2, A[4]); \
            A[5] = ffma2(p5, W0, A[5]); A[5] = ffma2(p6, W1, A[5]); A[5] = ffma2(p7, W2, A[5]); \
            A[6] = ffma2(p6, W0, A[6]); A[6] = ffma2(p7, W1, A[6]); \
        } \
    } while (0)

    COMPUTE(0, a0, a1, a2);
    LOADW(a0, a1, a2, 3);                // L1 hit by now (7 warps share lines)
    COMPUTE(1, b0, b1, b2);
    COMPUTE(2, c0, c1, c2);
    COMPUTE(3, a0, a1, a2);

    // ---- merge i-halves: ih=1 -> smem, barrier, ih=0 adds + REDG ----
    float2* red = reinterpret_cast<float2*>(sm + OFF_RED);
    if (ih == 1) {
#pragma unroll
        for (int m = 0; m < 7; m++)
            red[(n * 32 + lane) * 7 + m] = *reinterpret_cast<float2*>(&A[m]);
    }
    __syncthreads();

    if (ih == 0) {
        int nOut = n + 1; if (nOut == 7) nOut = 0;     // height roll +1
        float* d0 = out + (k0 + lane) * 49 + nOut * 7;        // group 0
        float* d1 = out + (512 + k0 + lane) * 49 + nOut * 7;  // group 1
#pragma unroll
        for (int m = 0; m < 7; m++) {
            float2 a = *reinterpret_cast<float2*>(&A[m]);
            float2 b = red[(n * 32 + lane) * 7 + m];
            atomicAdd(d0 + m, a.x + b.x);
            atomicAdd(d1 + m, a.y + b.y);
        }
    }
}

extern "C" void kernel_launch(void* const* d_in, const int* in_sizes, int n_in,
                              void* d_out, int out_size)
{
    const float* x = (const float*)d_in[0];
    const float* w = (const float*)d_in[1];
    float* out = (float*)d_out;

    cudaMemsetAsync(out, 0, (size_t)out_size * sizeof(float));
    conv_l1w<<<dim3(16, 8), THREADS, SMEM_TOT>>>(x, w, out);
}